// round 7
// baseline (speedup 1.0000x reference)
#include <cuda_runtime.h>
#include <math.h>
#include <cstdint>

// Problem constants
#define BB 2
#define SS 2048
#define DD 1024
#define HH 16
#define DH 64
#define FF 4096
#define ROWS (BB*SS)          // 4096
#define WINDOW 128
#define NGLOB 16
#define NEGV -1e9f

// weight offsets inside g_wr
#define OFF_WIN  0
#define OFF_WOUT (3*DD*DD)
#define OFF_W1   (OFF_WOUT + DD*DD)
#define OFF_W2   (OFF_W1 + FF*DD)
#define WTOTAL   (OFF_W2 + DD*FF)

// ---------------- scratch ----------------
__device__ float g_hln[ROWS * DD];
__device__ float g_qkv[ROWS * 3 * DD];
__device__ float g_o  [ROWS * DD];
__device__ float g_x1 [ROWS * DD];
__device__ float g_h2 [ROWS * FF];
__device__ float g_wr [WTOTAL];

// ---------------- helpers ----------------
__device__ __forceinline__ float tf32rf(float f) {
    uint32_t u;
    asm("cvt.rna.tf32.f32 %0, %1;" : "=r"(u) : "f"(f));
    return __uint_as_float(u);
}
__device__ __forceinline__ uint32_t smem_u32(const void* p) {
    uint32_t a;
    asm("{ .reg .u64 t; cvta.to.shared.u64 t, %1; cvt.u32.u64 %0, t; }" : "=r"(a) : "l"(p));
    return a;
}
#define CP_ASYNC16(sdst, gsrc) \
    asm volatile("cp.async.cg.shared.global [%0], [%1], 16;" :: "r"(sdst), "l"(gsrc))
#define CP_COMMIT() asm volatile("cp.async.commit_group;" ::: "memory")
#define CP_WAIT1()  asm volatile("cp.async.wait_group 1;" ::: "memory")

#define LDSM_X4(r0, r1, r2, r3, addr) \
    asm volatile("ldmatrix.sync.aligned.m8n8.x4.shared.b16 {%0,%1,%2,%3}, [%4];" \
        : "=r"(r0), "=r"(r1), "=r"(r2), "=r"(r3) : "r"(addr))

#define MMA_TF32(c, a, b) \
    asm volatile("mma.sync.aligned.m16n8k8.row.col.f32.tf32.tf32.f32 " \
        "{%0,%1,%2,%3}, {%4,%5,%6,%7}, {%8,%9}, {%0,%1,%2,%3};" \
        : "+f"((c)[0]), "+f"((c)[1]), "+f"((c)[2]), "+f"((c)[3]) \
        : "r"((a)[0]), "r"((a)[1]), "r"((a)[2]), "r"((a)[3]), \
          "r"((b)[0]), "r"((b)[1]))

// ---------------- weight tf32 pre-round ----------------
__global__ __launch_bounds__(256) void wprep_kernel(const float* __restrict__ w_in,
                                                    const float* __restrict__ w_out,
                                                    const float* __restrict__ w1,
                                                    const float* __restrict__ w2)
{
    long i = ((long)blockIdx.x * 256 + threadIdx.x) * 4;
    float4 v;
    if (i < OFF_WOUT)      v = *(const float4*)(w_in + i);
    else if (i < OFF_W1)   v = *(const float4*)(w_out + (i - OFF_WOUT));
    else if (i < OFF_W2)   v = *(const float4*)(w1 + (i - OFF_W1));
    else                   v = *(const float4*)(w2 + (i - OFF_W2));
    v.x = tf32rf(v.x); v.y = tf32rf(v.y); v.z = tf32rf(v.z); v.w = tf32rf(v.w);
    *(float4*)(g_wr + i) = v;
}

// ---------------- tf32 mma.sync GEMM ----------------
// CTA tile 256(M) x 128(N), BK=32, 3-stage cp.async.
// 8 warps as 4M x 2N, warp tile 64x64 (4 m16 x 8 n8 fragments).
#define RSTR 144                            // smem row stride bytes (36 floats)
#define A_STAGE (256 * RSTR)                // 36864
#define B_STAGE (128 * RSTR)                // 18432
#define NSTAGES 3
#define GEMM_SMEM (NSTAGES * (A_STAGE + B_STAGE))   // 165888

template <bool GELU, bool RES, bool RTF>
__global__ __launch_bounds__(256, 1) void gemm_mma(const float* __restrict__ A,
                                                   const float* __restrict__ W,
                                                   const float* __restrict__ bias,
                                                   const float* __restrict__ res,
                                                   float* __restrict__ C,
                                                   int M, int N, int K)
{
    extern __shared__ char smem[];
    uint32_t sA = smem_u32(smem);
    uint32_t sB = sA + NSTAGES * A_STAGE;

    int tid = threadIdx.x;
    int lane = tid & 31, wid = tid >> 5;
    int m0 = blockIdx.y * 256;
    int n0 = blockIdx.x * 128;
    int wm = (wid & 3) * 64;           // warp M offset (4 warps over 256)
    int wn = (wid >> 2) * 64;          // warp N offset (2 warps over 128)

    // cp.async mapping: chunk f = tid + i*256: row = f>>3, 16B col = f&7
    int r0 = tid >> 3;                 // 0..31
    int c16 = tid & 7;                 // 0..7
    const float* Agp = A + (long)(m0 + r0) * K + c16 * 4;
    const float* Bgp = W + (long)(n0 + r0) * K + c16 * 4;
    uint32_t sa = sA + r0 * RSTR + c16 * 16;
    uint32_t sb = sB + r0 * RSTR + c16 * 16;

#define ISSUE_STAGE(s) do { \
    long k0g = (long)(s) * 32; \
    uint32_t soa = ((s) % NSTAGES) * A_STAGE; \
    uint32_t sob = ((s) % NSTAGES) * B_STAGE; \
    _Pragma("unroll") \
    for (int i_ = 0; i_ < 8; i_++) \
        CP_ASYNC16(sa + soa + i_ * (32 * RSTR), Agp + (long)(32 * i_) * K + k0g); \
    _Pragma("unroll") \
    for (int i_ = 0; i_ < 4; i_++) \
        CP_ASYNC16(sb + sob + i_ * (32 * RSTR), Bgp + (long)(32 * i_) * K + k0g); \
    CP_COMMIT(); } while (0)

    // ldmatrix per-thread offsets
    int g = lane >> 3;
    int rl = lane & 7;
    uint32_t aoff = (uint32_t)(((g & 1) * 8 + rl + wm) * RSTR + (g >> 1) * 16);
    uint32_t boff = (uint32_t)(((g >> 1) * 8 + rl + wn) * RSTR + (g & 1) * 16);

    float acc[4][8][4];
#pragma unroll
    for (int i = 0; i < 4; i++)
#pragma unroll
        for (int j = 0; j < 8; j++)
#pragma unroll
            for (int c = 0; c < 4; c++) acc[i][j][c] = 0.f;

    int nIter = K >> 5;
    ISSUE_STAGE(0);
    ISSUE_STAGE(1);

    for (int it = 0; it < nIter; it++) {
        CP_WAIT1();
        __syncthreads();
        if (it + 2 < nIter) { ISSUE_STAGE(it + 2); } else { CP_COMMIT(); }

        uint32_t abase = sA + (uint32_t)((it % NSTAGES) * A_STAGE) + aoff;
        uint32_t bbase = sB + (uint32_t)((it % NSTAGES) * B_STAGE) + boff;
#pragma unroll
        for (int ks = 0; ks < 4; ks++) {
            uint32_t af[4][4], bf[8][2];
#pragma unroll
            for (int mi = 0; mi < 4; mi++)
                LDSM_X4(af[mi][0], af[mi][1], af[mi][2], af[mi][3],
                        abase + mi * (16 * RSTR) + ks * 32);
#pragma unroll
            for (int p = 0; p < 4; p++)
                LDSM_X4(bf[2*p][0], bf[2*p][1], bf[2*p+1][0], bf[2*p+1][1],
                        bbase + p * (16 * RSTR) + ks * 32);
#pragma unroll
            for (int mi = 0; mi < 4; mi++)
#pragma unroll
                for (int ni = 0; ni < 8; ni++)
                    MMA_TF32(acc[mi][ni], af[mi], bf[ni]);
        }
        // no bottom sync: top sync of it+1 protects slot reuse (3 stages, wait_group 1)
    }
#undef ISSUE_STAGE

    // epilogue
#pragma unroll
    for (int mi = 0; mi < 4; mi++) {
        long r_lo = m0 + wm + mi * 16 + (lane >> 2);
        long r_hi = r_lo + 8;
#pragma unroll
        for (int ni = 0; ni < 8; ni++) {
            int col = n0 + wn + ni * 8 + (lane & 3) * 2;
            float2 bv = *(const float2*)(bias + col);
            float v0 = acc[mi][ni][0] + bv.x;
            float v1 = acc[mi][ni][1] + bv.y;
            float v2 = acc[mi][ni][2] + bv.x;
            float v3 = acc[mi][ni][3] + bv.y;
            if (RES) {
                float2 rr0 = *(const float2*)(res + r_lo * N + col);
                float2 rr1 = *(const float2*)(res + r_hi * N + col);
                v0 += rr0.x; v1 += rr0.y; v2 += rr1.x; v3 += rr1.y;
            }
            if (GELU) {
                v0 = 0.5f * v0 * (1.0f + erff(v0 * 0.70710678118654752f));
                v1 = 0.5f * v1 * (1.0f + erff(v1 * 0.70710678118654752f));
                v2 = 0.5f * v2 * (1.0f + erff(v2 * 0.70710678118654752f));
                v3 = 0.5f * v3 * (1.0f + erff(v3 * 0.70710678118654752f));
            }
            if (RTF) {
                v0 = tf32rf(v0); v1 = tf32rf(v1); v2 = tf32rf(v2); v3 = tf32rf(v3);
            }
            *(float2*)(C + r_lo * N + col) = make_float2(v0, v1);
            *(float2*)(C + r_hi * N + col) = make_float2(v2, v3);
        }
    }
}

// ---------------- LayerNorm (outputs tf32-rounded) ----------------
__global__ __launch_bounds__(256) void ln_kernel(const float* __restrict__ x,
                                                 const float* __restrict__ g,
                                                 const float* __restrict__ bt,
                                                 float* __restrict__ out)
{
    int row = blockIdx.x;
    const float* xr = x + (long)row * DD;
    float v[4];
    float s = 0.f, s2 = 0.f;
#pragma unroll
    for (int i = 0; i < 4; i++) {
        v[i] = xr[threadIdx.x + i * 256];
        s += v[i];
        s2 += v[i] * v[i];
    }
    int lane = threadIdx.x & 31, warp = threadIdx.x >> 5;
#pragma unroll
    for (int off = 16; off > 0; off >>= 1) {
        s  += __shfl_xor_sync(0xffffffffu, s,  off);
        s2 += __shfl_xor_sync(0xffffffffu, s2, off);
    }
    __shared__ float sm[8], sm2[8];
    if (lane == 0) { sm[warp] = s; sm2[warp] = s2; }
    __syncthreads();
    if (threadIdx.x == 0) {
        float a = 0.f, b = 0.f;
#pragma unroll
        for (int i = 0; i < 8; i++) { a += sm[i]; b += sm2[i]; }
        float mean = a * (1.0f / DD);
        float var  = b * (1.0f / DD) - mean * mean;
        sm[0] = mean;
        sm2[0] = rsqrtf(var + 1e-5f);
    }
    __syncthreads();
    float mean = sm[0], inv = sm2[0];
    float* orow = out + (long)row * DD;
#pragma unroll
    for (int i = 0; i < 4; i++) {
        int c = threadIdx.x + i * 256;
        orow[c] = tf32rf((v[i] - mean) * inv * g[c] + bt[c]);
    }
}

// ---------------- mma-tiled sparse attention ----------------
#define QT 64
#define KP 256
#define QSTR 68
#define KSTR 68
#define VSTR 72
#define SSTR 260
#define ATTN_SMEM ((QT*QSTR + KP*VSTR + QT*SSTR + KP + QT) * 4)

__global__ __launch_bounds__(256, 1) void attn_mma(const float* __restrict__ qkv,
                                                   const int* __restrict__ am,
                                                   float* __restrict__ o)
{
    extern __shared__ float sf[];
    float* sQ  = sf;
    float* sKV = sQ + QT * QSTR;
    float* sS  = sKV + KP * VSTR;
    float* sAm = sS + QT * SSTR;
    float* sDen = sAm + KP;

    uint32_t sQb  = smem_u32(sQ);
    uint32_t sKVb = smem_u32(sKV);
    uint32_t sSb  = smem_u32(sS);

    int tid = threadIdx.x;
    int lane = tid & 31, wid = tid >> 5;
    int q0 = blockIdx.x * QT;
    int h = blockIdx.y & 15;
    int b = blockIdx.y >> 4;

    int koff = max(0, q0 - 128 - NGLOB);
    int NK = min(KP - 48, q0 + QT);

    const float* qbase = qkv + ((long)b * SS) * (3 * DD) + h * DH;

#pragma unroll
    for (int t = 0; t < 4; t++) {
        int f = tid + t * 256;
        int row = f >> 4, ch = f & 15;
        float4 v = *(const float4*)(qbase + (long)(q0 + row) * (3 * DD) + ch * 4);
        v.x = tf32rf(v.x); v.y = tf32rf(v.y); v.z = tf32rf(v.z); v.w = tf32rf(v.w);
        *(float4*)(sQ + row * QSTR + ch * 4) = v;
    }
#pragma unroll
    for (int t = 0; t < 16; t++) {
        int f = tid + t * 256;
        int idx = f >> 4, ch = f & 15;
        float4 v = make_float4(0.f, 0.f, 0.f, 0.f);
        if (idx < NK) {
            int key = idx + (idx < NGLOB ? 0 : koff);
            v = *(const float4*)(qbase + (long)key * (3 * DD) + DD + ch * 4);
            v.x = tf32rf(v.x); v.y = tf32rf(v.y); v.z = tf32rf(v.z); v.w = tf32rf(v.w);
        }
        *(float4*)(sKV + idx * KSTR + ch * 4) = v;
    }
    if (tid < KP) {
        int idx = tid;
        float a = NEGV;
        if (idx < NK) {
            int key = idx + (idx < NGLOB ? 0 : koff);
            a = (am[b * SS + key] == 0) ? NEGV : 0.f;
        }
        sAm[idx] = a;
    }
    __syncthreads();

    int g = lane >> 3;
    int rl = lane & 7;
    int wm = (wid & 1) * 32;
    int wn = (wid >> 1) * 64;
    {
        float acc[2][8][4];
#pragma unroll
        for (int i = 0; i < 2; i++)
#pragma unroll
            for (int j = 0; j < 8; j++)
#pragma unroll
                for (int c = 0; c < 4; c++) acc[i][j][c] = 0.f;

        uint32_t aQ = sQb + (wm + (g & 1) * 8 + rl) * (QSTR * 4) + (g >> 1) * 16;
        uint32_t bK = sKVb + (wn + (g >> 1) * 8 + rl) * (KSTR * 4) + (g & 1) * 16;
#pragma unroll
        for (int ks = 0; ks < 8; ks++) {
            uint32_t af[2][4], bf[8][2];
#pragma unroll
            for (int mt = 0; mt < 2; mt++)
                LDSM_X4(af[mt][0], af[mt][1], af[mt][2], af[mt][3],
                        aQ + mt * (16 * QSTR * 4) + ks * 32);
#pragma unroll
            for (int p = 0; p < 4; p++)
                LDSM_X4(bf[2*p][0], bf[2*p][1], bf[2*p+1][0], bf[2*p+1][1],
                        bK + p * (16 * KSTR * 4) + ks * 32);
#pragma unroll
            for (int mt = 0; mt < 2; mt++)
#pragma unroll
                for (int nt = 0; nt < 8; nt++)
                    MMA_TF32(acc[mt][nt], af[mt], bf[nt]);
        }

#pragma unroll
        for (int mt = 0; mt < 2; mt++) {
            int r0 = wm + mt * 16 + (lane >> 2);
            int r1 = r0 + 8;
            int qa0 = q0 + r0, qa1 = q0 + r1;
#pragma unroll
            for (int nt = 0; nt < 8; nt++) {
                int col = wn + nt * 8 + 2 * (lane & 3);
#pragma unroll
                for (int cc = 0; cc < 2; cc++) {
                    int cidx = col + cc;
                    int key = cidx + (cidx < NGLOB ? 0 : koff);
                    float amv = sAm[cidx];
                    bool ok0 = (cidx < NK) && (key <= qa0) && ((key < NGLOB) || (key >= qa0 - WINDOW));
                    bool ok1 = (cidx < NK) && (key <= qa1) && ((key < NGLOB) || (key >= qa1 - WINDOW));
                    sS[r0 * SSTR + cidx] = ok0 ? acc[mt][nt][cc] * 0.125f + amv : NEGV;
                    sS[r1 * SSTR + cidx] = ok1 ? acc[mt][nt][2 + cc] * 0.125f + amv : NEGV;
                }
            }
        }
    }
    __syncthreads();

#pragma unroll
    for (int t = 0; t < 16; t++) {
        int f = tid + t * 256;
        int idx = f >> 4, ch = f & 15;
        float4 v = make_float4(0.f, 0.f, 0.f, 0.f);
        if (idx < NK) {
            int key = idx + (idx < NGLOB ? 0 : koff);
            v = *(const float4*)(qbase + (long)key * (3 * DD) + 2 * DD + ch * 4);
            v.x = tf32rf(v.x); v.y = tf32rf(v.y); v.z = tf32rf(v.z); v.w = tf32rf(v.w);
        }
        *(float4*)(sKV + idx * VSTR + ch * 4) = v;
    }

#pragma unroll
    for (int i = 0; i < 8; i++) {
        int r = wid * 8 + i;
        float v[8];
#pragma unroll
        for (int j = 0; j < 8; j++) v[j] = sS[r * SSTR + lane + j * 32];
        float mx = v[0];
#pragma unroll
        for (int j = 1; j < 8; j++) mx = fmaxf(mx, v[j]);
#pragma unroll
        for (int off = 16; off > 0; off >>= 1) mx = fmaxf(mx, __shfl_xor_sync(0xffffffffu, mx, off));
        float sum = 0.f;
#pragma unroll
        for (int j = 0; j < 8; j++) {
            float e = __expf(v[j] - mx);
            e = tf32rf(e);
            sum += e;
            sS[r * SSTR + lane + j * 32] = e;
        }
#pragma unroll
        for (int off = 16; off > 0; off >>= 1) sum += __shfl_xor_sync(0xffffffffu, sum, off);
        if (lane == 0) sDen[r] = sum;
    }
    __syncthreads();

    {
        int wm2 = (wid & 3) * 16;
        int wn2 = (wid >> 2) * 32;
        float acc2[4][4];
#pragma unroll
        for (int j = 0; j < 4; j++)
#pragma unroll
            for (int c = 0; c < 4; c++) acc2[j][c] = 0.f;

        uint32_t aS = sSb + (wm2 + (g & 1) * 8 + rl) * (SSTR * 4) + (g >> 1) * 16;
#pragma unroll
        for (int ks = 0; ks < 32; ks++) {
            uint32_t af[4];
            LDSM_X4(af[0], af[1], af[2], af[3], aS + ks * 32);
            int k0 = ks * 8 + (lane & 3);
            int nb = wn2 + (lane >> 2);
            uint32_t bf[4][2];
#pragma unroll
            for (int nt = 0; nt < 4; nt++) {
                bf[nt][0] = __float_as_uint(sKV[k0 * VSTR + nb + nt * 8]);
                bf[nt][1] = __float_as_uint(sKV[(k0 + 4) * VSTR + nb + nt * 8]);
            }
#pragma unroll
            for (int nt = 0; nt < 4; nt++)
                MMA_TF32(acc2[nt], af, bf[nt]);
        }

        int r0o = wm2 + (lane >> 2);
        int r1o = r0o + 8;
        float inv0 = 1.f / sDen[r0o];
        float inv1 = 1.f / sDen[r1o];
        float* ob0 = o + ((long)(b * SS + q0 + r0o)) * DD + h * DH;
        float* ob1 = o + ((long)(b * SS + q0 + r1o)) * DD + h * DH;
#pragma unroll
        for (int nt = 0; nt < 4; nt++) {
            int col = wn2 + nt * 8 + 2 * (lane & 3);
            *(float2*)(ob0 + col) = make_float2(tf32rf(acc2[nt][0] * inv0), tf32rf(acc2[nt][1] * inv0));
            *(float2*)(ob1 + col) = make_float2(tf32rf(acc2[nt][2] * inv1), tf32rf(acc2[nt][3] * inv1));
        }
    }
}

// ---------------- launch ----------------
extern "C" void kernel_launch(void* const* d_in, const int* in_sizes, int n_in,
                              void* d_out, int out_size)
{
    const float* x     = (const float*)d_in[0];
    const int*   am    = (const int*)  d_in[1];
    const float* w_in  = (const float*)d_in[2];
    const float* b_in  = (const float*)d_in[3];
    const float* w_out = (const float*)d_in[4];
    const float* b_out = (const float*)d_in[5];
    const float* g1    = (const float*)d_in[6];
    const float* bl1   = (const float*)d_in[7];
    const float* g2    = (const float*)d_in[8];
    const float* bl2   = (const float*)d_in[9];
    const float* w1    = (const float*)d_in[10];
    const float* b1    = (const float*)d_in[11];
    const float* w2    = (const float*)d_in[12];
    const float* b2    = (const float*)d_in[13];
    float* out = (float*)d_out;

    void *p_hln, *p_qkv, *p_o, *p_x1, *p_h2, *p_wr;
    cudaGetSymbolAddress(&p_hln, g_hln);
    cudaGetSymbolAddress(&p_qkv, g_qkv);
    cudaGetSymbolAddress(&p_o,   g_o);
    cudaGetSymbolAddress(&p_x1,  g_x1);
    cudaGetSymbolAddress(&p_h2,  g_h2);
    cudaGetSymbolAddress(&p_wr,  g_wr);
    float* hln = (float*)p_hln;
    float* qkv = (float*)p_qkv;
    float* o   = (float*)p_o;
    float* x1  = (float*)p_x1;
    float* h2  = (float*)p_h2;
    float* wr  = (float*)p_wr;

    cudaFuncSetAttribute(gemm_mma<false, false, false>, cudaFuncAttributeMaxDynamicSharedMemorySize, GEMM_SMEM);
    cudaFuncSetAttribute(gemm_mma<false, true,  false>, cudaFuncAttributeMaxDynamicSharedMemorySize, GEMM_SMEM);
    cudaFuncSetAttribute(gemm_mma<true,  false, true >, cudaFuncAttributeMaxDynamicSharedMemorySize, GEMM_SMEM);
    cudaFuncSetAttribute(attn_mma, cudaFuncAttributeMaxDynamicSharedMemorySize, ATTN_SMEM);

    // 0. round weights to tf32
    wprep_kernel<<<WTOTAL / (256 * 4), 256>>>(w_in, w_out, w1, w2);
    // 1. LN1
    ln_kernel<<<ROWS, 256>>>(x, g1, bl1, hln);
    // 2. qkv = hln @ w_in^T + b_in
    gemm_mma<false, false, false><<<dim3(3 * DD / 128, ROWS / 256), 256, GEMM_SMEM>>>(hln, wr + OFF_WIN, b_in, nullptr, qkv, ROWS, 3 * DD, DD);
    // 3. attention -> o
    attn_mma<<<dim3(SS / QT, BB * HH), 256, ATTN_SMEM>>>(qkv, am, o);
    // 4. x1 = x + o @ w_out^T + b_out
    gemm_mma<false, true, false><<<dim3(DD / 128, ROWS / 256), 256, GEMM_SMEM>>>(o, wr + OFF_WOUT, b_out, x, x1, ROWS, DD, DD);
    // 5. LN2
    ln_kernel<<<ROWS, 256>>>(x1, g2, bl2, hln);
    // 6. h2 = gelu(hln @ w1^T + b1), tf32-rounded
    gemm_mma<true, false, true><<<dim3(FF / 128, ROWS / 256), 256, GEMM_SMEM>>>(hln, wr + OFF_W1, b1, nullptr, h2, ROWS, FF, DD);
    // 7. out = x1 + h2 @ w2^T + b2
    gemm_mma<false, true, false><<<dim3(DD / 128, ROWS / 256), 256, GEMM_SMEM>>>(h2, wr + OFF_W2, b2, x1, out, ROWS, DD, FF);
}

// round 8
// speedup vs baseline: 1.0580x; 1.0580x over previous
#include <cuda_runtime.h>
#include <math.h>
#include <cstdint>

// Problem constants
#define BB 2
#define SS 2048
#define DD 1024
#define HH 16
#define DH 64
#define FF 4096
#define ROWS (BB*SS)          // 4096
#define WINDOW 128
#define NGLOB 16
#define NEGV -1e9f

// weight offsets inside g_wr
#define OFF_WIN  0
#define OFF_WOUT (3*DD*DD)
#define OFF_W1   (OFF_WOUT + DD*DD)
#define OFF_W2   (OFF_W1 + FF*DD)
#define WTOTAL   (OFF_W2 + DD*FF)

// ---------------- scratch ----------------
__device__ float g_hln[ROWS * DD];
__device__ float g_qkv[ROWS * 3 * DD];
__device__ float g_o  [ROWS * DD];
__device__ float g_x1 [ROWS * DD];
__device__ float g_h2 [ROWS * FF];
__device__ float g_wr [WTOTAL];

// ---------------- helpers ----------------
__device__ __forceinline__ float tf32rf(float f) {
    uint32_t u;
    asm("cvt.rna.tf32.f32 %0, %1;" : "=r"(u) : "f"(f));
    return __uint_as_float(u);
}
__device__ __forceinline__ uint32_t smem_u32(const void* p) {
    uint32_t a;
    asm("{ .reg .u64 t; cvta.to.shared.u64 t, %1; cvt.u32.u64 %0, t; }" : "=r"(a) : "l"(p));
    return a;
}
#define CP_ASYNC16(sdst, gsrc) \
    asm volatile("cp.async.cg.shared.global [%0], [%1], 16;" :: "r"(sdst), "l"(gsrc))
#define CP_COMMIT() asm volatile("cp.async.commit_group;" ::: "memory")
#define CP_WAIT1()  asm volatile("cp.async.wait_group 1;" ::: "memory")

#define LDSM_X4(r0, r1, r2, r3, addr) \
    asm volatile("ldmatrix.sync.aligned.m8n8.x4.shared.b16 {%0,%1,%2,%3}, [%4];" \
        : "=r"(r0), "=r"(r1), "=r"(r2), "=r"(r3) : "r"(addr))

#define MMA_TF32(c, a, b) \
    asm volatile("mma.sync.aligned.m16n8k8.row.col.f32.tf32.tf32.f32 " \
        "{%0,%1,%2,%3}, {%4,%5,%6,%7}, {%8,%9}, {%0,%1,%2,%3};" \
        : "+f"((c)[0]), "+f"((c)[1]), "+f"((c)[2]), "+f"((c)[3]) \
        : "r"((a)[0]), "r"((a)[1]), "r"((a)[2]), "r"((a)[3]), \
          "r"((b)[0]), "r"((b)[1]))

// ---------------- weight tf32 pre-round ----------------
__global__ __launch_bounds__(256) void wprep_kernel(const float* __restrict__ w_in,
                                                    const float* __restrict__ w_out,
                                                    const float* __restrict__ w1,
                                                    const float* __restrict__ w2)
{
    long i = ((long)blockIdx.x * 256 + threadIdx.x) * 4;
    float4 v;
    if (i < OFF_WOUT)      v = *(const float4*)(w_in + i);
    else if (i < OFF_W1)   v = *(const float4*)(w_out + (i - OFF_WOUT));
    else if (i < OFF_W2)   v = *(const float4*)(w1 + (i - OFF_W1));
    else                   v = *(const float4*)(w2 + (i - OFF_W2));
    v.x = tf32rf(v.x); v.y = tf32rf(v.y); v.z = tf32rf(v.z); v.w = tf32rf(v.w);
    *(float4*)(g_wr + i) = v;
}

// ---------------- tf32 mma.sync GEMM ----------------
// CTA tile 128 x 128, BK=32, 3-stage cp.async, 4 warps (2M x 2N), warp tile 64x64.
// LDSM:MMA ratio 4.0 with 2 CTAs/SM and full grids.
#define RSTR 144                            // smem row stride bytes (36 floats)
#define STG  (128 * RSTR)                   // 18432 per matrix per stage
#define NSTAGES 3
#define GEMM_SMEM (2 * NSTAGES * STG)       // 110592

template <bool GELU, bool RES, bool RTF>
__global__ __launch_bounds__(128, 2) void gemm_mma(const float* __restrict__ A,
                                                   const float* __restrict__ W,
                                                   const float* __restrict__ bias,
                                                   const float* __restrict__ res,
                                                   float* __restrict__ C,
                                                   int M, int N, int K)
{
    extern __shared__ char smem[];
    uint32_t sA = smem_u32(smem);
    uint32_t sB = sA + NSTAGES * STG;

    int tid = threadIdx.x;
    int lane = tid & 31, wid = tid >> 5;     // 4 warps
    int m0 = blockIdx.y * 128;
    int n0 = blockIdx.x * 128;
    int wm = (wid & 1) * 64;
    int wn = (wid >> 1) * 64;

    // cp.async mapping (128 threads): r0 = tid>>3 (0..15), c16 = tid&7; 8 rows apart by 16
    int r0 = tid >> 3;
    int c16 = tid & 7;
    const float* Agp = A + (long)(m0 + r0) * K + c16 * 4;
    const float* Bgp = W + (long)(n0 + r0) * K + c16 * 4;
    uint32_t sa = sA + r0 * RSTR + c16 * 16;
    uint32_t sb = sB + r0 * RSTR + c16 * 16;

#define ISSUE_STAGE(s) do { \
    long k0g = (long)(s) * 32; \
    uint32_t so = ((s) % NSTAGES) * STG; \
    _Pragma("unroll") \
    for (int i_ = 0; i_ < 8; i_++) { \
        CP_ASYNC16(sa + so + i_ * (16 * RSTR), Agp + (long)(16 * i_) * K + k0g); \
        CP_ASYNC16(sb + so + i_ * (16 * RSTR), Bgp + (long)(16 * i_) * K + k0g); \
    } \
    CP_COMMIT(); } while (0)

    // ldmatrix per-thread offsets
    int g = lane >> 3;
    int rl = lane & 7;
    uint32_t aoff = (uint32_t)(((g & 1) * 8 + rl + wm) * RSTR + (g >> 1) * 16);
    uint32_t boff = (uint32_t)(((g >> 1) * 8 + rl + wn) * RSTR + (g & 1) * 16);

    float acc[4][8][4];
#pragma unroll
    for (int i = 0; i < 4; i++)
#pragma unroll
        for (int j = 0; j < 8; j++)
#pragma unroll
            for (int c = 0; c < 4; c++) acc[i][j][c] = 0.f;

    int nIter = K >> 5;
    ISSUE_STAGE(0);
    ISSUE_STAGE(1);

    for (int it = 0; it < nIter; it++) {
        CP_WAIT1();
        __syncthreads();
        if (it + 2 < nIter) { ISSUE_STAGE(it + 2); } else { CP_COMMIT(); }

        uint32_t slot = (uint32_t)((it % NSTAGES) * STG);
        uint32_t abase = sA + slot + aoff;
        uint32_t bbase = sB + slot + boff;
#pragma unroll
        for (int ks = 0; ks < 4; ks++) {
            uint32_t af[4][4], bf[8][2];
#pragma unroll
            for (int mi = 0; mi < 4; mi++)
                LDSM_X4(af[mi][0], af[mi][1], af[mi][2], af[mi][3],
                        abase + mi * (16 * RSTR) + ks * 32);
#pragma unroll
            for (int p = 0; p < 4; p++)
                LDSM_X4(bf[2*p][0], bf[2*p][1], bf[2*p+1][0], bf[2*p+1][1],
                        bbase + p * (16 * RSTR) + ks * 32);
#pragma unroll
            for (int mi = 0; mi < 4; mi++)
#pragma unroll
                for (int ni = 0; ni < 8; ni++)
                    MMA_TF32(acc[mi][ni], af[mi], bf[ni]);
        }
    }
#undef ISSUE_STAGE

    // epilogue
#pragma unroll
    for (int mi = 0; mi < 4; mi++) {
        long r_lo = m0 + wm + mi * 16 + (lane >> 2);
        long r_hi = r_lo + 8;
#pragma unroll
        for (int ni = 0; ni < 8; ni++) {
            int col = n0 + wn + ni * 8 + (lane & 3) * 2;
            float2 bv = *(const float2*)(bias + col);
            float v0 = acc[mi][ni][0] + bv.x;
            float v1 = acc[mi][ni][1] + bv.y;
            float v2 = acc[mi][ni][2] + bv.x;
            float v3 = acc[mi][ni][3] + bv.y;
            if (RES) {
                float2 rr0 = *(const float2*)(res + r_lo * N + col);
                float2 rr1 = *(const float2*)(res + r_hi * N + col);
                v0 += rr0.x; v1 += rr0.y; v2 += rr1.x; v3 += rr1.y;
            }
            if (GELU) {
                v0 = 0.5f * v0 * (1.0f + erff(v0 * 0.70710678118654752f));
                v1 = 0.5f * v1 * (1.0f + erff(v1 * 0.70710678118654752f));
                v2 = 0.5f * v2 * (1.0f + erff(v2 * 0.70710678118654752f));
                v3 = 0.5f * v3 * (1.0f + erff(v3 * 0.70710678118654752f));
            }
            if (RTF) {
                v0 = tf32rf(v0); v1 = tf32rf(v1); v2 = tf32rf(v2); v3 = tf32rf(v3);
            }
            *(float2*)(C + r_lo * N + col) = make_float2(v0, v1);
            *(float2*)(C + r_hi * N + col) = make_float2(v2, v3);
        }
    }
}

// ---------------- LayerNorm (outputs tf32-rounded) ----------------
__global__ __launch_bounds__(256) void ln_kernel(const float* __restrict__ x,
                                                 const float* __restrict__ g,
                                                 const float* __restrict__ bt,
                                                 float* __restrict__ out)
{
    int row = blockIdx.x;
    const float* xr = x + (long)row * DD;
    float v[4];
    float s = 0.f, s2 = 0.f;
#pragma unroll
    for (int i = 0; i < 4; i++) {
        v[i] = xr[threadIdx.x + i * 256];
        s += v[i];
        s2 += v[i] * v[i];
    }
    int lane = threadIdx.x & 31, warp = threadIdx.x >> 5;
#pragma unroll
    for (int off = 16; off > 0; off >>= 1) {
        s  += __shfl_xor_sync(0xffffffffu, s,  off);
        s2 += __shfl_xor_sync(0xffffffffu, s2, off);
    }
    __shared__ float sm[8], sm2[8];
    if (lane == 0) { sm[warp] = s; sm2[warp] = s2; }
    __syncthreads();
    if (threadIdx.x == 0) {
        float a = 0.f, b = 0.f;
#pragma unroll
        for (int i = 0; i < 8; i++) { a += sm[i]; b += sm2[i]; }
        float mean = a * (1.0f / DD);
        float var  = b * (1.0f / DD) - mean * mean;
        sm[0] = mean;
        sm2[0] = rsqrtf(var + 1e-5f);
    }
    __syncthreads();
    float mean = sm[0], inv = sm2[0];
    float* orow = out + (long)row * DD;
#pragma unroll
    for (int i = 0; i < 4; i++) {
        int c = threadIdx.x + i * 256;
        orow[c] = tf32rf((v[i] - mean) * inv * g[c] + bt[c]);
    }
}

// ---------------- mma-tiled sparse attention ----------------
#define QT 64
#define KP 256
#define QSTR 68
#define KSTR 68
#define VSTR 72
#define SSTR 260
#define ATTN_SMEM ((QT*QSTR + KP*VSTR + QT*SSTR + KP + QT) * 4)

__global__ __launch_bounds__(256, 1) void attn_mma(const float* __restrict__ qkv,
                                                   const int* __restrict__ am,
                                                   float* __restrict__ o)
{
    extern __shared__ float sf[];
    float* sQ  = sf;
    float* sKV = sQ + QT * QSTR;
    float* sS  = sKV + KP * VSTR;
    float* sAm = sS + QT * SSTR;
    float* sDen = sAm + KP;

    uint32_t sQb  = smem_u32(sQ);
    uint32_t sKVb = smem_u32(sKV);
    uint32_t sSb  = smem_u32(sS);

    int tid = threadIdx.x;
    int lane = tid & 31, wid = tid >> 5;
    int q0 = blockIdx.x * QT;
    int h = blockIdx.y & 15;
    int b = blockIdx.y >> 4;

    int koff = max(0, q0 - 128 - NGLOB);
    int NK = min(KP - 48, q0 + QT);

    const float* qbase = qkv + ((long)b * SS) * (3 * DD) + h * DH;

#pragma unroll
    for (int t = 0; t < 4; t++) {
        int f = tid + t * 256;
        int row = f >> 4, ch = f & 15;
        float4 v = *(const float4*)(qbase + (long)(q0 + row) * (3 * DD) + ch * 4);
        v.x = tf32rf(v.x); v.y = tf32rf(v.y); v.z = tf32rf(v.z); v.w = tf32rf(v.w);
        *(float4*)(sQ + row * QSTR + ch * 4) = v;
    }
#pragma unroll
    for (int t = 0; t < 16; t++) {
        int f = tid + t * 256;
        int idx = f >> 4, ch = f & 15;
        float4 v = make_float4(0.f, 0.f, 0.f, 0.f);
        if (idx < NK) {
            int key = idx + (idx < NGLOB ? 0 : koff);
            v = *(const float4*)(qbase + (long)key * (3 * DD) + DD + ch * 4);
            v.x = tf32rf(v.x); v.y = tf32rf(v.y); v.z = tf32rf(v.z); v.w = tf32rf(v.w);
        }
        *(float4*)(sKV + idx * KSTR + ch * 4) = v;
    }
    if (tid < KP) {
        int idx = tid;
        float a = NEGV;
        if (idx < NK) {
            int key = idx + (idx < NGLOB ? 0 : koff);
            a = (am[b * SS + key] == 0) ? NEGV : 0.f;
        }
        sAm[idx] = a;
    }
    __syncthreads();

    int g = lane >> 3;
    int rl = lane & 7;
    int wm = (wid & 1) * 32;
    int wn = (wid >> 1) * 64;
    {
        float acc[2][8][4];
#pragma unroll
        for (int i = 0; i < 2; i++)
#pragma unroll
            for (int j = 0; j < 8; j++)
#pragma unroll
                for (int c = 0; c < 4; c++) acc[i][j][c] = 0.f;

        uint32_t aQ = sQb + (wm + (g & 1) * 8 + rl) * (QSTR * 4) + (g >> 1) * 16;
        uint32_t bK = sKVb + (wn + (g >> 1) * 8 + rl) * (KSTR * 4) + (g & 1) * 16;
#pragma unroll
        for (int ks = 0; ks < 8; ks++) {
            uint32_t af[2][4], bf[8][2];
#pragma unroll
            for (int mt = 0; mt < 2; mt++)
                LDSM_X4(af[mt][0], af[mt][1], af[mt][2], af[mt][3],
                        aQ + mt * (16 * QSTR * 4) + ks * 32);
#pragma unroll
            for (int p = 0; p < 4; p++)
                LDSM_X4(bf[2*p][0], bf[2*p][1], bf[2*p+1][0], bf[2*p+1][1],
                        bK + p * (16 * KSTR * 4) + ks * 32);
#pragma unroll
            for (int mt = 0; mt < 2; mt++)
#pragma unroll
                for (int nt = 0; nt < 8; nt++)
                    MMA_TF32(acc[mt][nt], af[mt], bf[nt]);
        }

#pragma unroll
        for (int mt = 0; mt < 2; mt++) {
            int r0 = wm + mt * 16 + (lane >> 2);
            int r1 = r0 + 8;
            int qa0 = q0 + r0, qa1 = q0 + r1;
#pragma unroll
            for (int nt = 0; nt < 8; nt++) {
                int col = wn + nt * 8 + 2 * (lane & 3);
#pragma unroll
                for (int cc = 0; cc < 2; cc++) {
                    int cidx = col + cc;
                    int key = cidx + (cidx < NGLOB ? 0 : koff);
                    float amv = sAm[cidx];
                    bool ok0 = (cidx < NK) && (key <= qa0) && ((key < NGLOB) || (key >= qa0 - WINDOW));
                    bool ok1 = (cidx < NK) && (key <= qa1) && ((key < NGLOB) || (key >= qa1 - WINDOW));
                    sS[r0 * SSTR + cidx] = ok0 ? acc[mt][nt][cc] * 0.125f + amv : NEGV;
                    sS[r1 * SSTR + cidx] = ok1 ? acc[mt][nt][2 + cc] * 0.125f + amv : NEGV;
                }
            }
        }
    }
    __syncthreads();

#pragma unroll
    for (int t = 0; t < 16; t++) {
        int f = tid + t * 256;
        int idx = f >> 4, ch = f & 15;
        float4 v = make_float4(0.f, 0.f, 0.f, 0.f);
        if (idx < NK) {
            int key = idx + (idx < NGLOB ? 0 : koff);
            v = *(const float4*)(qbase + (long)key * (3 * DD) + 2 * DD + ch * 4);
            v.x = tf32rf(v.x); v.y = tf32rf(v.y); v.z = tf32rf(v.z); v.w = tf32rf(v.w);
        }
        *(float4*)(sKV + idx * VSTR + ch * 4) = v;
    }

#pragma unroll
    for (int i = 0; i < 8; i++) {
        int r = wid * 8 + i;
        float v[8];
#pragma unroll
        for (int j = 0; j < 8; j++) v[j] = sS[r * SSTR + lane + j * 32];
        float mx = v[0];
#pragma unroll
        for (int j = 1; j < 8; j++) mx = fmaxf(mx, v[j]);
#pragma unroll
        for (int off = 16; off > 0; off >>= 1) mx = fmaxf(mx, __shfl_xor_sync(0xffffffffu, mx, off));
        float sum = 0.f;
#pragma unroll
        for (int j = 0; j < 8; j++) {
            float e = __expf(v[j] - mx);
            e = tf32rf(e);
            sum += e;
            sS[r * SSTR + lane + j * 32] = e;
        }
#pragma unroll
        for (int off = 16; off > 0; off >>= 1) sum += __shfl_xor_sync(0xffffffffu, sum, off);
        if (lane == 0) sDen[r] = sum;
    }
    __syncthreads();

    {
        int wm2 = (wid & 3) * 16;
        int wn2 = (wid >> 2) * 32;
        float acc2[4][4];
#pragma unroll
        for (int j = 0; j < 4; j++)
#pragma unroll
            for (int c = 0; c < 4; c++) acc2[j][c] = 0.f;

        uint32_t aS = sSb + (wm2 + (g & 1) * 8 + rl) * (SSTR * 4) + (g >> 1) * 16;
#pragma unroll
        for (int ks = 0; ks < 32; ks++) {
            uint32_t af[4];
            LDSM_X4(af[0], af[1], af[2], af[3], aS + ks * 32);
            int k0 = ks * 8 + (lane & 3);
            int nb = wn2 + (lane >> 2);
            uint32_t bf[4][2];
#pragma unroll
            for (int nt = 0; nt < 4; nt++) {
                bf[nt][0] = __float_as_uint(sKV[k0 * VSTR + nb + nt * 8]);
                bf[nt][1] = __float_as_uint(sKV[(k0 + 4) * VSTR + nb + nt * 8]);
            }
#pragma unroll
            for (int nt = 0; nt < 4; nt++)
                MMA_TF32(acc2[nt], af, bf[nt]);
        }

        int r0o = wm2 + (lane >> 2);
        int r1o = r0o + 8;
        float inv0 = 1.f / sDen[r0o];
        float inv1 = 1.f / sDen[r1o];
        float* ob0 = o + ((long)(b * SS + q0 + r0o)) * DD + h * DH;
        float* ob1 = o + ((long)(b * SS + q0 + r1o)) * DD + h * DH;
#pragma unroll
        for (int nt = 0; nt < 4; nt++) {
            int col = wn2 + nt * 8 + 2 * (lane & 3);
            *(float2*)(ob0 + col) = make_float2(tf32rf(acc2[nt][0] * inv0), tf32rf(acc2[nt][1] * inv0));
            *(float2*)(ob1 + col) = make_float2(tf32rf(acc2[nt][2] * inv1), tf32rf(acc2[nt][3] * inv1));
        }
    }
}

// ---------------- launch ----------------
extern "C" void kernel_launch(void* const* d_in, const int* in_sizes, int n_in,
                              void* d_out, int out_size)
{
    const float* x     = (const float*)d_in[0];
    const int*   am    = (const int*)  d_in[1];
    const float* w_in  = (const float*)d_in[2];
    const float* b_in  = (const float*)d_in[3];
    const float* w_out = (const float*)d_in[4];
    const float* b_out = (const float*)d_in[5];
    const float* g1    = (const float*)d_in[6];
    const float* bl1   = (const float*)d_in[7];
    const float* g2    = (const float*)d_in[8];
    const float* bl2   = (const float*)d_in[9];
    const float* w1    = (const float*)d_in[10];
    const float* b1    = (const float*)d_in[11];
    const float* w2    = (const float*)d_in[12];
    const float* b2    = (const float*)d_in[13];
    float* out = (float*)d_out;

    void *p_hln, *p_qkv, *p_o, *p_x1, *p_h2, *p_wr;
    cudaGetSymbolAddress(&p_hln, g_hln);
    cudaGetSymbolAddress(&p_qkv, g_qkv);
    cudaGetSymbolAddress(&p_o,   g_o);
    cudaGetSymbolAddress(&p_x1,  g_x1);
    cudaGetSymbolAddress(&p_h2,  g_h2);
    cudaGetSymbolAddress(&p_wr,  g_wr);
    float* hln = (float*)p_hln;
    float* qkv = (float*)p_qkv;
    float* o   = (float*)p_o;
    float* x1  = (float*)p_x1;
    float* h2  = (float*)p_h2;
    float* wr  = (float*)p_wr;

    cudaFuncSetAttribute(gemm_mma<false, false, false>, cudaFuncAttributeMaxDynamicSharedMemorySize, GEMM_SMEM);
    cudaFuncSetAttribute(gemm_mma<false, true,  false>, cudaFuncAttributeMaxDynamicSharedMemorySize, GEMM_SMEM);
    cudaFuncSetAttribute(gemm_mma<true,  false, true >, cudaFuncAttributeMaxDynamicSharedMemorySize, GEMM_SMEM);
    cudaFuncSetAttribute(attn_mma, cudaFuncAttributeMaxDynamicSharedMemorySize, ATTN_SMEM);

    // 0. round weights to tf32
    wprep_kernel<<<WTOTAL / (256 * 4), 256>>>(w_in, w_out, w1, w2);
    // 1. LN1
    ln_kernel<<<ROWS, 256>>>(x, g1, bl1, hln);
    // 2. qkv = hln @ w_in^T + b_in
    gemm_mma<false, false, false><<<dim3(3 * DD / 128, ROWS / 128), 128, GEMM_SMEM>>>(hln, wr + OFF_WIN, b_in, nullptr, qkv, ROWS, 3 * DD, DD);
    // 3. attention -> o
    attn_mma<<<dim3(SS / QT, BB * HH), 256, ATTN_SMEM>>>(qkv, am, o);
    // 4. x1 = x + o @ w_out^T + b_out
    gemm_mma<false, true, false><<<dim3(DD / 128, ROWS / 128), 128, GEMM_SMEM>>>(o, wr + OFF_WOUT, b_out, x, x1, ROWS, DD, DD);
    // 5. LN2
    ln_kernel<<<ROWS, 256>>>(x1, g2, bl2, hln);
    // 6. h2 = gelu(hln @ w1^T + b1), tf32-rounded
    gemm_mma<true, false, true><<<dim3(FF / 128, ROWS / 128), 128, GEMM_SMEM>>>(hln, wr + OFF_W1, b1, nullptr, h2, ROWS, FF, DD);
    // 7. out = x1 + h2 @ w2^T + b2
    gemm_mma<false, true, false><<<dim3(DD / 128, ROWS / 128), 128, GEMM_SMEM>>>(h2, wr + OFF_W2, b2, x1, out, ROWS, DD, FF);
}